// round 1
// baseline (speedup 1.0000x reference)
#include <cuda_runtime.h>
#include <cstdint>
#include <cstddef>

#define Bb 512
#define Tt 512
#define Ff 128
#define Uu 256
#define G4 1024   // 4*U

// ---------------- device scratch (allocation-free rules: __device__ globals) ----
__device__ float g_xz[(size_t)Bb * Tt * G4];   // 1 GiB precomputed x@kernel+bias
__device__ float g_h[2][Bb][Uu];               // double-buffered hidden state
__device__ unsigned g_bar;                     // global barrier counter

// ---------------- reset (graph-replay safe re-init) ----------------
__global__ void reset_kernel() {
    size_t i = (size_t)blockIdx.x * blockDim.x + threadIdx.x;
    if (i < (size_t)Bb * Uu) (&g_h[0][0][0])[i] = 0.0f;
    if (i == 0) g_bar = 0u;
}

// ---------------- Phase 1: XZ = x @ kernel + bias  (M=B*T, N=1024, K=128) ----
#define P1_BM 128
#define P1_BN 64
#define P1_BK 32

__global__ __launch_bounds__(256) void xz_gemm(const float* __restrict__ x,
                                               const float* __restrict__ wk,
                                               const float* __restrict__ bias) {
    __shared__ float As[P1_BK][P1_BM + 1];   // stride 129: conflict-free transposed stores
    __shared__ float Bs[P1_BK][68];
    int tid  = threadIdx.x;
    int nblk = blockIdx.x, mblk = blockIdx.y;
    const float* xblk = x + (size_t)mblk * P1_BM * Ff;
    int tn = tid & 15, tm = tid >> 4;        // n0 = 4*tn, m0 = 8*tm

    float acc[8][4];
    float bv[4];
#pragma unroll
    for (int j = 0; j < 4; j++) bv[j] = bias[nblk * P1_BN + 4 * tn + j];
#pragma unroll
    for (int i = 0; i < 8; i++)
#pragma unroll
        for (int j = 0; j < 4; j++) acc[i][j] = bv[j];

    int lm = tid >> 3, lq = tid & 7;
    for (int kk = 0; kk < Ff; kk += P1_BK) {
#pragma unroll
        for (int p = 0; p < 4; p++) {
            float4 v = *(const float4*)(xblk + (size_t)(lm + 32 * p) * Ff + kk + 4 * lq);
            As[4 * lq + 0][lm + 32 * p] = v.x;
            As[4 * lq + 1][lm + 32 * p] = v.y;
            As[4 * lq + 2][lm + 32 * p] = v.z;
            As[4 * lq + 3][lm + 32 * p] = v.w;
        }
#pragma unroll
        for (int i = 0; i < 2; i++) {
            int fi = tid * 2 + i;
            int r = fi >> 4, c = fi & 15;
            float4 v = *(const float4*)(wk + (size_t)(kk + r) * G4 + nblk * P1_BN + 4 * c);
            *(float4*)&Bs[r][4 * c] = v;
        }
        __syncthreads();
#pragma unroll
        for (int k = 0; k < P1_BK; k++) {
            float a[8];
#pragma unroll
            for (int i = 0; i < 8; i++) a[i] = As[k][8 * tm + i];
            float4 b4 = *(const float4*)&Bs[k][4 * tn];
#pragma unroll
            for (int i = 0; i < 8; i++) {
                acc[i][0] += a[i] * b4.x;
                acc[i][1] += a[i] * b4.y;
                acc[i][2] += a[i] * b4.z;
                acc[i][3] += a[i] * b4.w;
            }
        }
        __syncthreads();
    }
    float* od = g_xz + ((size_t)mblk * P1_BM) * G4 + nblk * P1_BN;
#pragma unroll
    for (int i = 0; i < 8; i++) {
        float4 v = make_float4(acc[i][0], acc[i][1], acc[i][2], acc[i][3]);
        *(float4*)(od + (size_t)(8 * tm + i) * G4 + 4 * tn) = v;
    }
}

// ---------------- Phase 2: persistent recurrence --------------------
// 128 CTAs = 16 batch-groups x 8 column-groups. Each CTA: 32 batches x 32 units
// (x4 gates = 128 output columns). rec_kernel slice (256x128 fp32 = 128 KB) lives
// in SMEM, interleaved [k][uu*4+g] so one float4 = 4 gates of one unit.
// Cell state c lives in registers. h exchanged through g_h (double buffered in L2)
// with a custom all-resident global barrier per step.
#define RC_CTAS 128

__global__ __launch_bounds__(256, 1) void lstm_rec(const float* __restrict__ rk,
                                                   const float* __restrict__ dw,
                                                   const float* __restrict__ db,
                                                   float* __restrict__ out) {
    extern __shared__ float sm[];
    float* Wr = sm;               // [256][128] interleaved
    float* Hs = sm + 256 * 128;   // [32][260] (padded stride, 16B-aligned rows)

    int tid   = threadIdx.x;
    int bg    = blockIdx.x >> 3;
    int cg    = blockIdx.x & 7;
    int bbase = bg * 32;
    int ubase = cg * 32;

    // one-time: load + interleave weight slice
    for (int idx = tid; idx < 256 * 128; idx += 256) {
        int k = idx >> 7, n = idx & 127;
        int uu = n >> 2, g = n & 3;
        Wr[idx] = rk[(size_t)k * G4 + g * Uu + ubase + uu];
    }
    int w = tid >> 5, uu = tid & 31;   // warp w -> batches 4w..4w+3, lane -> unit
    int ug = ubase + uu;
    float c0 = 0.f, c1 = 0.f, c2 = 0.f, c3 = 0.f;
    __syncthreads();

    int sb = tid >> 3, sq = tid & 7;   // h-staging map
    unsigned target = 0;

    for (int t = 0; t < Tt; t++) {
        // stage h_prev tile (32x256) from L2 into SMEM
        {
            const float* hsrc = &g_h[t & 1][bbase + sb][0];
            float* hdst = Hs + sb * 260;
#pragma unroll
            for (int j = 0; j < 8; j++)
                *(float4*)(hdst + 4 * sq + 32 * j) = *(const float4*)(hsrc + 4 * sq + 32 * j);
        }
        // init accumulators with precomputed xz (loads issue early, consumed late)
        float acc[4][4];
#pragma unroll
        for (int i = 0; i < 4; i++) {
            const float* p = g_xz + ((size_t)(bbase + 4 * w + i) * Tt + t) * G4 + ug;
            acc[i][0] = p[0];
            acc[i][1] = p[Uu];
            acc[i][2] = p[2 * Uu];
            acc[i][3] = p[3 * Uu];
        }
        __syncthreads();

        const float* h0p = Hs + (4 * w + 0) * 260;
        const float* h1p = Hs + (4 * w + 1) * 260;
        const float* h2p = Hs + (4 * w + 2) * 260;
        const float* h3p = Hs + (4 * w + 3) * 260;
        const float* wp  = Wr + 4 * uu;
#pragma unroll 8
        for (int k = 0; k < 256; k++) {
            float4 wv = *(const float4*)(wp + (size_t)k * 128);
            float h0 = h0p[k], h1 = h1p[k], h2 = h2p[k], h3 = h3p[k];
            acc[0][0] += h0 * wv.x; acc[0][1] += h0 * wv.y; acc[0][2] += h0 * wv.z; acc[0][3] += h0 * wv.w;
            acc[1][0] += h1 * wv.x; acc[1][1] += h1 * wv.y; acc[1][2] += h1 * wv.z; acc[1][3] += h1 * wv.w;
            acc[2][0] += h2 * wv.x; acc[2][1] += h2 * wv.y; acc[2][2] += h2 * wv.z; acc[2][3] += h2 * wv.w;
            acc[3][0] += h3 * wv.x; acc[3][1] += h3 * wv.y; acc[3][2] += h3 * wv.z; acc[3][3] += h3 * wv.w;
        }

        // gates: i,f sigmoid / g relu / o sigmoid ; h = o * relu(c)
        float hn[4];
        float cc[4] = {c0, c1, c2, c3};
#pragma unroll
        for (int i = 0; i < 4; i++) {
            float ig = 1.f / (1.f + __expf(-acc[i][0]));
            float fg = 1.f / (1.f + __expf(-acc[i][1]));
            float gg = fmaxf(acc[i][2], 0.f);
            float og = 1.f / (1.f + __expf(-acc[i][3]));
            float cn = fg * cc[i] + ig * gg;
            cc[i] = cn;
            hn[i] = og * fmaxf(cn, 0.f);
        }
        c0 = cc[0]; c1 = cc[1]; c2 = cc[2]; c3 = cc[3];

        float* hd = &g_h[(t + 1) & 1][0][0];
#pragma unroll
        for (int i = 0; i < 4; i++)
            hd[(size_t)(bbase + 4 * w + i) * Uu + ug] = hn[i];

        // global barrier (all 128 CTAs co-resident: 1 CTA/SM by smem, grid<=SMs)
        __syncthreads();
        if (tid == 0) {
            __threadfence();
            atomicAdd(&g_bar, 1u);
            target += RC_CTAS;
            while (*((volatile unsigned*)&g_bar) < target) { }
            __threadfence();
        }
        __syncthreads();
    }

    // final dense: out[b] = h_T[b,:] . dw + db   (h_T lives in g_h[0]; T even)
    if (cg == 0) {
        int b = tid >> 3, r = tid & 7;
        const float* hrow = &g_h[0][bbase + b][0];
        float s = 0.f;
#pragma unroll
        for (int j = 0; j < 32; j++) s += hrow[r + 8 * j] * dw[r + 8 * j];
        s += __shfl_down_sync(0xffffffffu, s, 4);
        s += __shfl_down_sync(0xffffffffu, s, 2);
        s += __shfl_down_sync(0xffffffffu, s, 1);
        if (r == 0) out[bbase + b] = s + db[0];
    }
}

// ---------------- launch ----------------
extern "C" void kernel_launch(void* const* d_in, const int* in_sizes, int n_in,
                              void* d_out, int out_size) {
    const float* x    = (const float*)d_in[0];
    const float* wk   = (const float*)d_in[1];
    const float* rk   = (const float*)d_in[2];
    const float* bias = (const float*)d_in[3];
    const float* dw   = (const float*)d_in[4];
    const float* db   = (const float*)d_in[5];
    float* out = (float*)d_out;

    size_t smem = (size_t)(256 * 128 + 32 * 260) * sizeof(float);  // 164352 B
    cudaFuncSetAttribute(lstm_rec, cudaFuncAttributeMaxDynamicSharedMemorySize, (int)smem);

    reset_kernel<<<(Bb * Uu + 255) / 256, 256>>>();
    xz_gemm<<<dim3(G4 / P1_BN, (Bb * Tt) / P1_BM), 256>>>(x, wk, bias);
    lstm_rec<<<RC_CTAS, 256, smem>>>(rk, dw, db, out);
}